// round 1
// baseline (speedup 1.0000x reference)
#include <cuda_runtime.h>
#include <cuda_bf16.h>

#define D_MODEL 1024
#define N_EXPERTS 8
#define HIDDEN 2048
#define T_MAX 4096
#define NPAIR (T_MAX * 2)

#define BM 64
#define BN 64
#define BK 16

// ---- static scratch (no allocations allowed) ----
__device__ int   g_cnt[N_EXPERTS];
__device__ int   g_entry[N_EXPERTS][T_MAX];   // pairid = t*2 + k
__device__ float g_gate[NPAIR];               // routing weight per pair
__device__ float g_h[(size_t)NPAIR * HIDDEN]; // 64 MB SwiGLU activations

// ---------------------------------------------------------------------------
// Kernel 0: reset counters + zero output (out is poisoned by harness)
// ---------------------------------------------------------------------------
__global__ void reset_kernel(float* __restrict__ out, int n) {
    int i = blockIdx.x * blockDim.x + threadIdx.x;
    if (i < N_EXPERTS) g_cnt[i] = 0;
    int n4 = n >> 2;
    float4 z = make_float4(0.f, 0.f, 0.f, 0.f);
    for (int j = i; j < n4; j += gridDim.x * blockDim.x)
        reinterpret_cast<float4*>(out)[j] = z;
    // tail (n not multiple of 4) — handled by first few threads
    int tail = n & 3;
    if (i < tail) out[n4 * 4 + i] = 0.f;
}

// ---------------------------------------------------------------------------
// Kernel 1: router — logits, softmax, top-2, dispatch lists
// one warp per token
// ---------------------------------------------------------------------------
__global__ void router_kernel(const float* __restrict__ x,
                              const float* __restrict__ wr, int T) {
    int warp = (blockIdx.x * blockDim.x + threadIdx.x) >> 5;
    int lane = threadIdx.x & 31;
    if (warp >= T) return;

    const float* xrow = x + (size_t)warp * D_MODEL;
    float acc[N_EXPERTS];
#pragma unroll
    for (int e = 0; e < N_EXPERTS; e++) acc[e] = 0.f;

    for (int d = lane; d < D_MODEL; d += 32) {
        float xv = xrow[d];
        const float4* wp = reinterpret_cast<const float4*>(wr + (size_t)d * N_EXPERTS);
        float4 w0 = wp[0], w1 = wp[1];
        acc[0] += xv * w0.x; acc[1] += xv * w0.y;
        acc[2] += xv * w0.z; acc[3] += xv * w0.w;
        acc[4] += xv * w1.x; acc[5] += xv * w1.y;
        acc[6] += xv * w1.z; acc[7] += xv * w1.w;
    }
#pragma unroll
    for (int e = 0; e < N_EXPERTS; e++) {
#pragma unroll
        for (int off = 16; off > 0; off >>= 1)
            acc[e] += __shfl_xor_sync(0xffffffffu, acc[e], off);
    }

    if (lane == 0) {
        float mx = acc[0];
#pragma unroll
        for (int e = 1; e < N_EXPERTS; e++) mx = fmaxf(mx, acc[e]);
        float p[N_EXPERTS];
        float s = 0.f;
#pragma unroll
        for (int e = 0; e < N_EXPERTS; e++) { p[e] = __expf(acc[e] - mx); s += p[e]; }
        float inv = 1.f / s;
        int i1 = 0;
#pragma unroll
        for (int e = 1; e < N_EXPERTS; e++) if (p[e] > p[i1]) i1 = e;
        int i2 = (i1 == 0) ? 1 : 0;
#pragma unroll
        for (int e = 0; e < N_EXPERTS; e++)
            if (e != i1 && p[e] > p[i2]) i2 = e;

        int t = warp;
        int pos = atomicAdd(&g_cnt[i1], 1);
        g_entry[i1][pos] = t * 2 + 0;
        g_gate[t * 2 + 0] = p[i1] * inv;
        pos = atomicAdd(&g_cnt[i2], 1);
        g_entry[i2][pos] = t * 2 + 1;
        g_gate[t * 2 + 1] = p[i2] * inv;
    }
}

// ---------------------------------------------------------------------------
// Kernel 2: grouped GEMM1 + SwiGLU
// per expert e: for its tokens, h = silu(x @ w1[e]) * (x @ w3[e]) -> g_h
// block computes BMxBN tile, both w1 and w3 branches (x tile reused)
// ---------------------------------------------------------------------------
__global__ __launch_bounds__(256, 2)
void gemm1_kernel(const float* __restrict__ x,
                  const float* __restrict__ w1,
                  const float* __restrict__ w3) {
    int e   = blockIdx.z;
    int cnt = g_cnt[e];
    int m0  = blockIdx.y * BM;
    if (m0 >= cnt) return;
    int n0 = blockIdx.x * BN;

    __shared__ float As[BK][BM];
    __shared__ float B1s[BK][BN];
    __shared__ float B3s[BK][BN];
    __shared__ int   sPair[BM];

    int tid = threadIdx.x;
    if (tid < BM) {
        int r = m0 + tid;
        sPair[tid] = (r < cnt) ? g_entry[e][r] : -1;
    }
    __syncthreads();

    // A gather setup: thread loads one float4 of x per K-iter
    int arow = tid >> 2;            // 0..63
    int akq  = (tid & 3) * 4;       // 0,4,8,12
    int pa   = sPair[arow];
    const float* aptr = (pa >= 0)
        ? (x + (size_t)(pa >> 1) * D_MODEL + akq) : nullptr;

    // B loads: thread loads one float4 per B tile per K-iter
    int bk = tid >> 4;              // 0..15
    int bn = (tid & 15) * 4;        // 0..60
    const float* b1ptr = w1 + (size_t)e * D_MODEL * HIDDEN + (size_t)bk * HIDDEN + n0 + bn;
    const float* b3ptr = w3 + (size_t)e * D_MODEL * HIDDEN + (size_t)bk * HIDDEN + n0 + bn;

    int ty = tid >> 4, tx = tid & 15;
    float acc1[4][4] = {}, acc3[4][4] = {};

    for (int k0 = 0; k0 < D_MODEL; k0 += BK) {
        float4 av = aptr ? *reinterpret_cast<const float4*>(aptr + k0)
                         : make_float4(0.f, 0.f, 0.f, 0.f);
        float4 b1v = *reinterpret_cast<const float4*>(b1ptr + (size_t)k0 * HIDDEN);
        float4 b3v = *reinterpret_cast<const float4*>(b3ptr + (size_t)k0 * HIDDEN);
        __syncthreads();
        As[akq + 0][arow] = av.x;
        As[akq + 1][arow] = av.y;
        As[akq + 2][arow] = av.z;
        As[akq + 3][arow] = av.w;
        *reinterpret_cast<float4*>(&B1s[bk][bn]) = b1v;
        *reinterpret_cast<float4*>(&B3s[bk][bn]) = b3v;
        __syncthreads();
#pragma unroll
        for (int kk = 0; kk < BK; kk++) {
            float4 a  = *reinterpret_cast<float4*>(&As[kk][ty * 4]);
            float4 b1 = *reinterpret_cast<float4*>(&B1s[kk][tx * 4]);
            float4 b3 = *reinterpret_cast<float4*>(&B3s[kk][tx * 4]);
            float ar[4] = {a.x, a.y, a.z, a.w};
            float b1r[4] = {b1.x, b1.y, b1.z, b1.w};
            float b3r[4] = {b3.x, b3.y, b3.z, b3.w};
#pragma unroll
            for (int i = 0; i < 4; i++)
#pragma unroll
                for (int j = 0; j < 4; j++) {
                    acc1[i][j] = fmaf(ar[i], b1r[j], acc1[i][j]);
                    acc3[i][j] = fmaf(ar[i], b3r[j], acc3[i][j]);
                }
        }
    }

    // epilogue: SwiGLU -> g_h
#pragma unroll
    for (int i = 0; i < 4; i++) {
        int r  = ty * 4 + i;
        int pr = sPair[r];
        if (pr < 0) continue;
        float* hrow = g_h + (size_t)pr * HIDDEN + n0 + tx * 4;
        float4 o;
        float h1, sg;
        h1 = acc1[i][0]; sg = 1.f / (1.f + __expf(-h1)); o.x = h1 * sg * acc3[i][0];
        h1 = acc1[i][1]; sg = 1.f / (1.f + __expf(-h1)); o.y = h1 * sg * acc3[i][1];
        h1 = acc1[i][2]; sg = 1.f / (1.f + __expf(-h1)); o.z = h1 * sg * acc3[i][2];
        h1 = acc1[i][3]; sg = 1.f / (1.f + __expf(-h1)); o.w = h1 * sg * acc3[i][3];
        *reinterpret_cast<float4*>(hrow) = o;
    }
}

// ---------------------------------------------------------------------------
// Kernel 3: grouped GEMM2 + weighted combine (atomicAdd into out)
// y = h @ w2[e]; out[t] += gate * y
// ---------------------------------------------------------------------------
__global__ __launch_bounds__(256, 3)
void gemm2_kernel(const float* __restrict__ w2, float* __restrict__ out) {
    int e   = blockIdx.z;
    int cnt = g_cnt[e];
    int m0  = blockIdx.y * BM;
    if (m0 >= cnt) return;
    int n0 = blockIdx.x * BN;

    __shared__ float As[BK][BM];
    __shared__ float Bs[BK][BN];
    __shared__ int   sPair[BM];

    int tid = threadIdx.x;
    if (tid < BM) {
        int r = m0 + tid;
        sPair[tid] = (r < cnt) ? g_entry[e][r] : -1;
    }
    __syncthreads();

    int arow = tid >> 2;
    int akq  = (tid & 3) * 4;
    int pa   = sPair[arow];
    const float* aptr = (pa >= 0)
        ? (g_h + (size_t)pa * HIDDEN + akq) : nullptr;

    int bk = tid >> 4;
    int bn = (tid & 15) * 4;
    const float* bptr = w2 + (size_t)e * HIDDEN * D_MODEL + (size_t)bk * D_MODEL + n0 + bn;

    int ty = tid >> 4, tx = tid & 15;
    float acc[4][4] = {};

    for (int k0 = 0; k0 < HIDDEN; k0 += BK) {
        float4 av = aptr ? *reinterpret_cast<const float4*>(aptr + k0)
                         : make_float4(0.f, 0.f, 0.f, 0.f);
        float4 bv = *reinterpret_cast<const float4*>(bptr + (size_t)k0 * D_MODEL);
        __syncthreads();
        As[akq + 0][arow] = av.x;
        As[akq + 1][arow] = av.y;
        As[akq + 2][arow] = av.z;
        As[akq + 3][arow] = av.w;
        *reinterpret_cast<float4*>(&Bs[bk][bn]) = bv;
        __syncthreads();
#pragma unroll
        for (int kk = 0; kk < BK; kk++) {
            float4 a = *reinterpret_cast<float4*>(&As[kk][ty * 4]);
            float4 b = *reinterpret_cast<float4*>(&Bs[kk][tx * 4]);
            float ar[4] = {a.x, a.y, a.z, a.w};
            float br[4] = {b.x, b.y, b.z, b.w};
#pragma unroll
            for (int i = 0; i < 4; i++)
#pragma unroll
                for (int j = 0; j < 4; j++)
                    acc[i][j] = fmaf(ar[i], br[j], acc[i][j]);
        }
    }

#pragma unroll
    for (int i = 0; i < 4; i++) {
        int r  = ty * 4 + i;
        int pr = sPair[r];
        if (pr < 0) continue;
        int   t = pr >> 1;
        float g = g_gate[pr];
        float* op = out + (size_t)t * D_MODEL + n0 + tx * 4;
        atomicAdd(op + 0, g * acc[i][0]);
        atomicAdd(op + 1, g * acc[i][1]);
        atomicAdd(op + 2, g * acc[i][2]);
        atomicAdd(op + 3, g * acc[i][3]);
    }
}

// ---------------------------------------------------------------------------
extern "C" void kernel_launch(void* const* d_in, const int* in_sizes, int n_in,
                              void* d_out, int out_size) {
    const float* x  = (const float*)d_in[0];
    const float* wr = (const float*)d_in[1];
    const float* w1 = (const float*)d_in[2];
    const float* w3 = (const float*)d_in[3];
    const float* w2 = (const float*)d_in[4];
    float* out = (float*)d_out;

    int T = in_sizes[0] / D_MODEL;   // 4096

    reset_kernel<<<1024, 256>>>(out, out_size);
    router_kernel<<<(T + 7) / 8, 256>>>(x, wr, T);

    int mtiles = (T + BM - 1) / BM;  // worst case: one expert gets all tokens
    dim3 g1(HIDDEN / BN, mtiles, N_EXPERTS);
    gemm1_kernel<<<g1, 256>>>(x, w1, w3);

    dim3 g2(D_MODEL / BN, mtiles, N_EXPERTS);
    gemm2_kernel<<<g2, 256>>>(w2, out);
}

// round 15
// speedup vs baseline: 2.3845x; 2.3845x over previous
#include <cuda_runtime.h>
#include <cstdint>

#define D_MODEL 1024
#define N_EXPERTS 8
#define HIDDEN 2048
#define T_MAX 4096
#define NPAIR (T_MAX * 2)
#define WSEG (N_EXPERTS * D_MODEL * HIDDEN)

// ---- static scratch ----
__device__ int   g_cnt[N_EXPERTS];
__device__ int   g_entry[N_EXPERTS][T_MAX];     // pairid = t*2 + k
__device__ float g_gate[NPAIR];
__device__ float g_h[(size_t)NPAIR * HIDDEN];   // SwiGLU activations (tf32-rounded)
__device__ float g_w1t[WSEG];                   // tf32 (RNA) rounded copies
__device__ float g_w3t[WSEG];
__device__ float g_w2t[WSEG];
__device__ float g_xt[(size_t)T_MAX * D_MODEL];

// ---- smem geometry ----
#define AS_STRIDE 48                      // floats per A row
#define BS_STRIDE 130                     // floats per B k-row
#define A_BYTES (128 * AS_STRIDE * 4)     // 24576
#define B_BYTES (32 * BS_STRIDE * 4)      // 16640
#define STAGE   (A_BYTES + B_BYTES)       // 41216
#define OFF_PAIR (2 * STAGE)              // 82432
#define SMEM_SZ (OFF_PAIR + 1536)

// ============================ helpers ============================
__device__ __forceinline__ uint32_t s2u(const void* p) {
    uint32_t a;
    asm("{ .reg .u64 t; cvta.to.shared.u64 t, %1; cvt.u32.u64 %0, t; }" : "=r"(a) : "l"(p));
    return a;
}
__device__ __forceinline__ void cp16z(uint32_t d, const void* s, int sz) {
    asm volatile("cp.async.ca.shared.global [%0], [%1], 16, %2;" :: "r"(d), "l"(s), "r"(sz));
}
__device__ __forceinline__ void cp8(uint32_t d, const void* s) {
    asm volatile("cp.async.ca.shared.global [%0], [%1], 8;" :: "r"(d), "l"(s));
}
#define CP_COMMIT() asm volatile("cp.async.commit_group;" ::: "memory")
#define CP_WAIT1()  asm volatile("cp.async.wait_group 1;" ::: "memory")
#define LDS128(r0,r1,r2,r3,addr) \
    asm volatile("ld.shared.v4.b32 {%0,%1,%2,%3},[%4];" \
                 : "=r"(r0),"=r"(r1),"=r"(r2),"=r"(r3) : "r"(addr))
#define LDS32(r0,addr) \
    asm volatile("ld.shared.b32 %0,[%1];" : "=r"(r0) : "r"(addr))

__device__ __forceinline__ float cvt_tf32(float f) {
    uint32_t u;
    asm("cvt.rna.tf32.f32 %0, %1;" : "=r"(u) : "f"(f));
    return __uint_as_float(u);
}
__device__ __forceinline__ void mma8(float& d0, float& d1, float& d2, float& d3,
                                     uint32_t a0, uint32_t a1, uint32_t a2, uint32_t a3,
                                     uint32_t b0, uint32_t b1) {
    asm volatile(
        "mma.sync.aligned.m16n8k8.row.col.f32.tf32.tf32.f32 "
        "{%0,%1,%2,%3}, {%4,%5,%6,%7}, {%8,%9}, {%0,%1,%2,%3};"
        : "+f"(d0), "+f"(d1), "+f"(d2), "+f"(d3)
        : "r"(a0), "r"(a1), "r"(a2), "r"(a3), "r"(b0), "r"(b1));
}
__device__ __forceinline__ float silu_f(float x) { return x / (1.f + __expf(-x)); }

// ============================ Kernel 0: reset out ============================
__global__ void reset_kernel(float* __restrict__ out, int n) {
    int i = blockIdx.x * blockDim.x + threadIdx.x;
    if (i < N_EXPERTS) g_cnt[i] = 0;
    int n4 = n >> 2;
    float4 z = make_float4(0.f, 0.f, 0.f, 0.f);
    for (int j = i; j < n4; j += gridDim.x * blockDim.x)
        reinterpret_cast<float4*>(out)[j] = z;
    int tail = n & 3;
    if (i < tail) out[n4 * 4 + i] = 0.f;
}

// ============================ Kernel 0b: tf32 RNA pre-round ============================
__global__ void cvt_all(const float* __restrict__ w1, const float* __restrict__ w3,
                        const float* __restrict__ w2, const float* __restrict__ x, int nx4) {
    const int W4 = WSEG / 4;
    const int total = 3 * W4 + nx4;
    for (int i = blockIdx.x * blockDim.x + threadIdx.x; i < total;
         i += gridDim.x * blockDim.x) {
        const float4* src; float4* dst; int j;
        if (i < W4)          { src = (const float4*)w1; dst = (float4*)g_w1t; j = i; }
        else if (i < 2 * W4) { src = (const float4*)w3; dst = (float4*)g_w3t; j = i - W4; }
        else if (i < 3 * W4) { src = (const float4*)w2; dst = (float4*)g_w2t; j = i - 2 * W4; }
        else                 { src = (const float4*)x;  dst = (float4*)g_xt;  j = i - 3 * W4; }
        float4 v = src[j];
        v.x = cvt_tf32(v.x); v.y = cvt_tf32(v.y);
        v.z = cvt_tf32(v.z); v.w = cvt_tf32(v.w);
        dst[j] = v;
    }
}

// ============================ Kernel 1: router ============================
__global__ void router_kernel(const float* __restrict__ x,
                              const float* __restrict__ wr, int T) {
    int warp = (blockIdx.x * blockDim.x + threadIdx.x) >> 5;
    int lane = threadIdx.x & 31;
    if (warp >= T) return;

    const float* xrow = x + (size_t)warp * D_MODEL;
    float acc[N_EXPERTS];
#pragma unroll
    for (int e = 0; e < N_EXPERTS; e++) acc[e] = 0.f;
    for (int d = lane; d < D_MODEL; d += 32) {
        float xv = xrow[d];
        const float4* wp = reinterpret_cast<const float4*>(wr + (size_t)d * N_EXPERTS);
        float4 w0 = wp[0], w1 = wp[1];
        acc[0] += xv * w0.x; acc[1] += xv * w0.y;
        acc[2] += xv * w0.z; acc[3] += xv * w0.w;
        acc[4] += xv * w1.x; acc[5] += xv * w1.y;
        acc[6] += xv * w1.z; acc[7] += xv * w1.w;
    }
#pragma unroll
    for (int e = 0; e < N_EXPERTS; e++) {
#pragma unroll
        for (int off = 16; off > 0; off >>= 1)
            acc[e] += __shfl_xor_sync(0xffffffffu, acc[e], off);
    }
    if (lane == 0) {
        float mx = acc[0];
#pragma unroll
        for (int e = 1; e < N_EXPERTS; e++) mx = fmaxf(mx, acc[e]);
        float p[N_EXPERTS]; float s = 0.f;
#pragma unroll
        for (int e = 0; e < N_EXPERTS; e++) { p[e] = __expf(acc[e] - mx); s += p[e]; }
        float inv = 1.f / s;
        int i1 = 0;
#pragma unroll
        for (int e = 1; e < N_EXPERTS; e++) if (p[e] > p[i1]) i1 = e;
        int i2 = (i1 == 0) ? 1 : 0;
#pragma unroll
        for (int e = 0; e < N_EXPERTS; e++)
            if (e != i1 && p[e] > p[i2]) i2 = e;
        int t = warp;
        int pos = atomicAdd(&g_cnt[i1], 1);
        g_entry[i1][pos] = t * 2 + 0;
        g_gate[t * 2 + 0] = p[i1] * inv;
        pos = atomicAdd(&g_cnt[i2], 1);
        g_entry[i2][pos] = t * 2 + 1;
        g_gate[t * 2 + 1] = p[i2] * inv;
    }
}

// ============================ Kernel 2: GEMM1 (mma.sync tf32) ============================
// h = silu(x@w1)*(x@w3). CTA tile: 128 M x 64 N per matrix (B cols 0-63 w1, 64-127 w3).
__global__ __launch_bounds__(256) void gemm1_mma() {
    extern __shared__ __align__(16) char smem[];
    const int e   = blockIdx.z;
    const int cnt = g_cnt[e];
    const int m0  = blockIdx.y * 128;
    if (m0 >= cnt) return;
    const int n0  = blockIdx.x * 64;

    const int tid  = threadIdx.x;
    const int wid  = tid >> 5;
    const int lane = tid & 31;
    const int g    = lane >> 2;
    const int tq   = lane & 3;
    const int wm   = (wid & 1) * 64;
    const int wn   = (wid >> 1) * 16;

    const uint32_t sb = s2u(smem);
    int* sPair = (int*)(smem + OFF_PAIR);
    if (tid < 128) {
        int r = m0 + tid;
        sPair[tid] = (r < cnt) ? g_entry[e][r] : -1;
    }
    __syncthreads();

    const int arow = tid >> 1;
    const int au   = (tid & 1) * 16;
    const int pa   = sPair[arow];
    const float* asrc = g_xt + (size_t)(pa < 0 ? 0 : (pa >> 1)) * D_MODEL + au;
    const int a_ok = (pa >= 0) ? 16 : 0;
    const int bkr = tid >> 3;
    const int bu  = tid & 7;
    const float* w1e = g_w1t + (size_t)e * D_MODEL * HIDDEN;
    const float* w3e = g_w3t + (size_t)e * D_MODEL * HIDDEN;

    float acc[4][4][4];
#pragma unroll
    for (int i = 0; i < 4; i++)
#pragma unroll
        for (int j = 0; j < 4; j++) {
            acc[i][j][0] = 0.f; acc[i][j][1] = 0.f;
            acc[i][j][2] = 0.f; acc[i][j][3] = 0.f;
        }

    const int NC = D_MODEL / 32;
    // ---- stage 0 ----
    {
        uint32_t ad = sb + (arow * AS_STRIDE + au) * 4;
        cp16z(ad, asrc, a_ok); cp16z(ad + 16, asrc + 4, a_ok);
        cp16z(ad + 32, asrc + 8, a_ok); cp16z(ad + 48, asrc + 12, a_ok);
        uint32_t bd = sb + A_BYTES + (bkr * BS_STRIDE) * 4;
        const float* r1 = w1e + (size_t)bkr * HIDDEN + n0;
        const float* r3 = w3e + (size_t)bkr * HIDDEN + n0;
#pragma unroll
        for (int j = 0; j < 8; j++) {
            int c16 = j * 16 + 2 * bu;
            cp8(bd + c16 * 4, (j < 4) ? (r1 + c16) : (r3 + c16 - 64));
        }
    }
    CP_COMMIT();

#pragma unroll 1
    for (int c = 0; c < NC; c++) {
        if (c + 1 < NC) {
            const int s = (c + 1) & 1, kofs = (c + 1) * 32;
            uint32_t ad = sb + s * STAGE + (arow * AS_STRIDE + au) * 4;
            const float* as = asrc + kofs;
            cp16z(ad, as, a_ok); cp16z(ad + 16, as + 4, a_ok);
            cp16z(ad + 32, as + 8, a_ok); cp16z(ad + 48, as + 12, a_ok);
            uint32_t bd = sb + s * STAGE + A_BYTES + (bkr * BS_STRIDE) * 4;
            const float* r1 = w1e + (size_t)(kofs + bkr) * HIDDEN + n0;
            const float* r3 = w3e + (size_t)(kofs + bkr) * HIDDEN + n0;
#pragma unroll
            for (int j = 0; j < 8; j++) {
                int c16 = j * 16 + 2 * bu;
                cp8(bd + c16 * 4, (j < 4) ? (r1 + c16) : (r3 + c16 - 64));
            }
        }
        CP_COMMIT();
        CP_WAIT1();
        __syncthreads();
        const uint32_t ab = sb + (c & 1) * STAGE;
        const uint32_t bb = ab + A_BYTES;
#pragma unroll
        for (int h2 = 0; h2 < 2; h2++) {
            const int kb = h2 * 16;
            uint32_t Ar[4][8];
#pragma unroll
            for (int mi = 0; mi < 4; mi++) {
                uint32_t ad = ab + ((wm + mi * 16 + g) * AS_STRIDE + kb + 4 * tq) * 4;
                LDS128(Ar[mi][0], Ar[mi][1], Ar[mi][2], Ar[mi][3], ad);
                LDS128(Ar[mi][4], Ar[mi][5], Ar[mi][6], Ar[mi][7],
                       ad + 8 * AS_STRIDE * 4);
            }
#pragma unroll
            for (int nj = 0; nj < 4; nj++) {
                const int col = (nj >> 1) * 64 + wn + (nj & 1) * 8 + g;
                uint32_t Br[4];
                uint32_t bad = bb + ((kb + 4 * tq) * BS_STRIDE + col) * 4;
                LDS32(Br[0], bad);
                LDS32(Br[1], bad + BS_STRIDE * 4);
                LDS32(Br[2], bad + 2 * BS_STRIDE * 4);
                LDS32(Br[3], bad + 3 * BS_STRIDE * 4);
#pragma unroll
                for (int mi = 0; mi < 4; mi++) {
                    mma8(acc[mi][nj][0], acc[mi][nj][1], acc[mi][nj][2], acc[mi][nj][3],
                         Ar[mi][0], Ar[mi][4], Ar[mi][1], Ar[mi][5], Br[0], Br[1]);
                    mma8(acc[mi][nj][0], acc[mi][nj][1], acc[mi][nj][2], acc[mi][nj][3],
                         Ar[mi][2], Ar[mi][6], Ar[mi][3], Ar[mi][7], Br[2], Br[3]);
                }
            }
        }
        __syncthreads();
    }

    // ---- epilogue: SwiGLU, tf32-round, direct store to g_h ----
#pragma unroll
    for (int mi = 0; mi < 4; mi++) {
        const int rlo = wm + mi * 16 + g;
        const int rhi = rlo + 8;
        const int plo = sPair[rlo], phi = sPair[rhi];
#pragma unroll
        for (int nj = 0; nj < 2; nj++) {
            const int col = n0 + wn + nj * 8 + 2 * tq;
            float* c1 = acc[mi][nj];
            float* c3 = acc[mi][nj + 2];
            if (plo >= 0) {
                float2 v = make_float2(cvt_tf32(silu_f(c1[0]) * c3[0]),
                                       cvt_tf32(silu_f(c1[1]) * c3[1]));
                *reinterpret_cast<float2*>(&g_h[(size_t)plo * HIDDEN + col]) = v;
            }
            if (phi >= 0) {
                float2 v = make_float2(cvt_tf32(silu_f(c1[2]) * c3[2]),
                                       cvt_tf32(silu_f(c1[3]) * c3[3]));
                *reinterpret_cast<float2*>(&g_h[(size_t)phi * HIDDEN + col]) = v;
            }
        }
    }
}

// ============================ Kernel 3: GEMM2 (mma.sync tf32) + combine ============================
__global__ __launch_bounds__(256) void gemm2_mma(float* __restrict__ out) {
    extern __shared__ __align__(16) char smem[];
    const int e   = blockIdx.z;
    const int cnt = g_cnt[e];
    const int m0  = blockIdx.y * 128;
    if (m0 >= cnt) return;
    const int n0  = blockIdx.x * 128;

    const int tid  = threadIdx.x;
    const int wid  = tid >> 5;
    const int lane = tid & 31;
    const int g    = lane >> 2;
    const int tq   = lane & 3;
    const int wm   = (wid & 1) * 64;
    const int wn   = (wid >> 1) * 32;

    const uint32_t sb = s2u(smem);
    int*   sPair = (int*)(smem + OFF_PAIR);
    int*   sTok  = (int*)(smem + OFF_PAIR + 512);
    float* sGate = (float*)(smem + OFF_PAIR + 1024);
    if (tid < 128) {
        int r = m0 + tid;
        int pr = (r < cnt) ? g_entry[e][r] : -1;
        sPair[tid] = pr;
        sTok[tid]  = (pr >= 0) ? (pr >> 1) : -1;
        sGate[tid] = (pr >= 0) ? g_gate[pr] : 0.f;
    }
    __syncthreads();

    const int arow = tid >> 1;
    const int au   = (tid & 1) * 16;
    const int pa   = sPair[arow];
    const float* asrc = g_h + (size_t)(pa < 0 ? 0 : pa) * HIDDEN + au;
    const int a_ok = (pa >= 0) ? 16 : 0;
    const int bkr = tid >> 3;
    const int bu  = tid & 7;
    const float* w2e = g_w2t + (size_t)e * HIDDEN * D_MODEL;

    float acc[4][4][4];
#pragma unroll
    for (int i = 0; i < 4; i++)
#pragma unroll
        for (int j = 0; j < 4; j++) {
            acc[i][j][0] = 0.f; acc[i][j][1] = 0.f;
            acc[i][j][2] = 0.f; acc[i][j][3] = 0.f;
        }

    const int NC = HIDDEN / 32;
    {
        uint32_t ad = sb + (arow * AS_STRIDE + au) * 4;
        cp16z(ad, asrc, a_ok); cp16z(ad + 16, asrc + 4, a_ok);
        cp16z(ad + 32, asrc + 8, a_ok); cp16z(ad + 48, asrc + 12, a_ok);
        uint32_t bd = sb + A_BYTES + (bkr * BS_STRIDE) * 4;
        const float* r2 = w2e + (size_t)bkr * D_MODEL + n0;
#pragma unroll
        for (int j = 0; j < 8; j++) {
            int c16 = j * 16 + 2 * bu;
            cp8(bd + c16 * 4, r2 + c16);
        }
    }
    CP_COMMIT();

#pragma unroll 1
    for (int c = 0; c < NC; c++) {
        if (c + 1 < NC) {
            const int s = (c + 1) & 1, kofs = (c + 1) * 32;
            uint32_t ad = sb + s * STAGE + (arow * AS_STRIDE + au) * 4;
            const float* as = asrc + kofs;
            cp16z(ad, as, a_ok); cp16z(ad + 16, as + 4, a_ok);
            cp16z(ad + 32, as + 8, a_ok); cp16z(ad + 48, as + 12, a_ok);
            uint32_t bd = sb + s * STAGE + A_BYTES + (bkr * BS_STRIDE) * 4;
            const float* r2 = w2e + (size_t)(kofs + bkr) * D_MODEL + n0;
#pragma unroll
            for (int j = 0; j < 8; j++) {
                int c16 = j * 16 + 2 * bu;
                cp8(bd + c16 * 4, r2 + c16);
            }
        }
        CP_COMMIT();
        CP_WAIT1();
        __syncthreads();
        const uint32_t ab = sb + (c & 1) * STAGE;
        const uint32_t bb = ab + A_BYTES;
#pragma unroll
        for (int h2 = 0; h2 < 2; h2++) {
            const int kb = h2 * 16;
            uint32_t Ar[4][8];
#pragma unroll
            for (int mi = 0; mi < 4; mi++) {
                uint32_t ad = ab + ((wm + mi * 16 + g) * AS_STRIDE + kb + 4 * tq) * 4;
                LDS128(Ar[mi][0], Ar[mi][1], Ar[mi][2], Ar[mi][3], ad);
                LDS128(Ar[mi][4], Ar[mi][5], Ar[mi][6], Ar[mi][7],
                       ad + 8 * AS_STRIDE * 4);
            }
#pragma unroll
            for (int nj = 0; nj < 4; nj++) {
                const int col = wn + nj * 8 + g;
                uint32_t Br[4];
                uint32_t bad = bb + ((kb + 4 * tq) * BS_STRIDE + col) * 4;
                LDS32(Br[0], bad);
                LDS32(Br[1], bad + BS_STRIDE * 4);
                LDS32(Br[2], bad + 2 * BS_STRIDE * 4);
                LDS32(Br[3], bad + 3 * BS_STRIDE * 4);
#pragma unroll
                for (int mi = 0; mi < 4; mi++) {
                    mma8(acc[mi][nj][0], acc[mi][nj][1], acc[mi][nj][2], acc[mi][nj][3],
                         Ar[mi][0], Ar[mi][4], Ar[mi][1], Ar[mi][5], Br[0], Br[1]);
                    mma8(acc[mi][nj][0], acc[mi][nj][1], acc[mi][nj][2], acc[mi][nj][3],
                         Ar[mi][2], Ar[mi][6], Ar[mi][3], Ar[mi][7], Br[2], Br[3]);
                }
            }
        }
        __syncthreads();
    }

    // ---- epilogue: gate*y, atomicAdd into out ----
#pragma unroll
    for (int mi = 0; mi < 4; mi++) {
        const int rlo = wm + mi * 16 + g;
        const int rhi = rlo + 8;
        const int tlo = sTok[rlo], thi = sTok[rhi];
        const float glo = sGate[rlo], ghi = sGate[rhi];
#pragma unroll
        for (int nj = 0; nj < 4; nj++) {
            const int col = n0 + wn + nj * 8 + 2 * tq;
            float* cc = acc[mi][nj];
            if (tlo >= 0) {
                float* op = out + (size_t)tlo * D_MODEL + col;
                atomicAdd(op,     glo * cc[0]);
                atomicAdd(op + 1, glo * cc[1]);
            }
            if (thi >= 0) {
                float* op = out + (size_t)thi * D_MODEL + col;
                atomicAdd(op,     ghi * cc[2]);
                atomicAdd(op + 1, ghi * cc[3]);
            }
        }
    }
}

// ============================ launch ============================
extern "C" void kernel_launch(void* const* d_in, const int* in_sizes, int n_in,
                              void* d_out, int out_size) {
    const float* x  = (const float*)d_in[0];
    const float* wr = (const float*)d_in[1];
    const float* w1 = (const float*)d_in[2];
    const float* w3 = (const float*)d_in[3];
    const float* w2 = (const float*)d_in[4];
    float* out = (float*)d_out;

    int T = in_sizes[0] / D_MODEL;  // 4096

    cudaFuncSetAttribute(gemm1_mma, cudaFuncAttributeMaxDynamicSharedMemorySize, SMEM_SZ);
    cudaFuncSetAttribute(gemm2_mma, cudaFuncAttributeMaxDynamicSharedMemorySize, SMEM_SZ);

    reset_kernel<<<1024, 256>>>(out, out_size);
    cvt_all<<<2048, 256>>>(w1, w3, w2, x, (T * D_MODEL) / 4);
    router_kernel<<<(T + 7) / 8, 256>>>(x, wr, T);

    int mtiles = (T + 127) / 128;   // worst case per expert
    dim3 g1(HIDDEN / 64, mtiles, N_EXPERTS);
    gemm1_mma<<<g1, 256, SMEM_SZ>>>();

    dim3 g2(D_MODEL / 128, mtiles, N_EXPERTS);
    gemm2_mma<<<g2, 256, SMEM_SZ>>>(out);
}